// round 1
// baseline (speedup 1.0000x reference)
#include <cuda_runtime.h>
#include <cuda_bf16.h>
#include <math.h>

// Problem dims
#define VV 16000
#define BB 32
#define TT 256
#define EE 512
#define GE 2048          // 4*E
#define MROWS 8192       // B*T

// ---------------- scratch (device globals; no allocation allowed) -------------
__device__ float g_Xs  [(size_t)MROWS * EE];     // xs time-major [t*B+b][E]
__device__ float g_G   [(size_t)MROWS * GE];     // precomputed x@Wx+b (reused per layer)
__device__ float g_H0T [(size_t)TT * EE * BB];   // layer0 h history, per-t transposed [E][B]
__device__ float g_H0RM[(size_t)MROWS * EE];     // layer0 h, row-major time-major (A for X1 gemm)
__device__ float g_H1T [(size_t)TT * EE * BB];   // layer1 h history transposed
__device__ float g_H1RM[(size_t)MROWS * EE];     // layer1 h, row-major BATCH-major (A for logits)
__device__ float g_C0  [EE * BB];                // cell state layer0, transposed [E][B]
__device__ float g_C1  [EE * BB];
__device__ float g_nll [MROWS];

// ---------------- small helpers ----------------
__device__ __forceinline__ float sigm(float x) { return 1.0f / (1.0f + expf(-x)); }

// ---------------- zero cell states ----------------
__global__ void zero_state_kernel() {
    int i = blockIdx.x * blockDim.x + threadIdx.x;
    if (i < EE * BB) { g_C0[i] = 0.0f; g_C1[i] = 0.0f; }
}

// ---------------- embedding gather: xs[(t*B+b)*E + e] = Emat[inputs[b*T+t]*E + e]
__global__ void embed_kernel(const int* __restrict__ inputs, const float* __restrict__ Emat) {
    int idx = blockIdx.x * blockDim.x + threadIdx.x;      // over MROWS * (E/4)
    if (idx >= MROWS * (EE / 4)) return;
    int r  = idx >> 7;        // row (t*B+b),   E/4 = 128
    int e4 = idx & 127;
    int t = r >> 5;           // /B
    int b = r & 31;
    int tok = inputs[b * TT + t];
    reinterpret_cast<float4*>(g_Xs)[(size_t)r * 128 + e4] =
        reinterpret_cast<const float4*>(Emat)[(size_t)tok * 128 + e4];
}

// ---------------- SGEMM: C[M,N] = A[M,K] * B[K,N] + bias[N] ----------------
// BM=BN=128, BK=8, 256 threads, 8x8 per thread, double-buffered smem.
// Requires M%128==0, N%128==0, K%8==0 (true for all call sites).
#define BM 128
#define BN 128
#define BK 8

__global__ __launch_bounds__(256, 2)
void sgemm_bias(const float* __restrict__ A, const float* __restrict__ Bm,
                const float* __restrict__ bias, float* __restrict__ C,
                int M, int N, int K)
{
    __shared__ __align__(16) float As[2][BK][BM];
    __shared__ __align__(16) float Bs[2][BK][BN];

    int tid = threadIdx.x;
    int n0 = blockIdx.x * BN;
    int m0 = blockIdx.y * BM;

    int aRow = tid >> 1;          // 0..127
    int aK   = (tid & 1) * 4;     // 0 or 4
    int bK   = tid >> 5;          // 0..7
    int bN   = (tid & 31) * 4;    // 0..124

    int tx = tid & 15;
    int ty = tid >> 4;

    const float* Aptr = A + (size_t)(m0 + aRow) * K + aK;
    const float* Bptr = Bm + (size_t)bK * N + n0 + bN;

    float4 a_ld = *reinterpret_cast<const float4*>(Aptr);
    float4 b_ld = *reinterpret_cast<const float4*>(Bptr);

    As[0][aK + 0][aRow] = a_ld.x;
    As[0][aK + 1][aRow] = a_ld.y;
    As[0][aK + 2][aRow] = a_ld.z;
    As[0][aK + 3][aRow] = a_ld.w;
    *reinterpret_cast<float4*>(&Bs[0][bK][bN]) = b_ld;
    __syncthreads();

    float acc[8][8];
    #pragma unroll
    for (int i = 0; i < 8; i++)
        #pragma unroll
        for (int j = 0; j < 8; j++) acc[i][j] = 0.0f;

    int NT = K / BK;
    int buf = 0;
    for (int kt = 0; kt < NT; kt++) {
        if (kt + 1 < NT) {
            a_ld = *reinterpret_cast<const float4*>(Aptr + (kt + 1) * BK);
            b_ld = *reinterpret_cast<const float4*>(Bptr + (size_t)(kt + 1) * BK * N);
        }
        #pragma unroll
        for (int k = 0; k < BK; k++) {
            float4 a0 = *reinterpret_cast<float4*>(&As[buf][k][ty * 4]);
            float4 a1 = *reinterpret_cast<float4*>(&As[buf][k][ty * 4 + 64]);
            float4 b0 = *reinterpret_cast<float4*>(&Bs[buf][k][tx * 4]);
            float4 b1 = *reinterpret_cast<float4*>(&Bs[buf][k][tx * 4 + 64]);
            float av[8] = {a0.x, a0.y, a0.z, a0.w, a1.x, a1.y, a1.z, a1.w};
            float bv[8] = {b0.x, b0.y, b0.z, b0.w, b1.x, b1.y, b1.z, b1.w};
            #pragma unroll
            for (int i = 0; i < 8; i++)
                #pragma unroll
                for (int j = 0; j < 8; j++)
                    acc[i][j] += av[i] * bv[j];
        }
        if (kt + 1 < NT) {
            buf ^= 1;
            As[buf][aK + 0][aRow] = a_ld.x;
            As[buf][aK + 1][aRow] = a_ld.y;
            As[buf][aK + 2][aRow] = a_ld.z;
            As[buf][aK + 3][aRow] = a_ld.w;
            *reinterpret_cast<float4*>(&Bs[buf][bK][bN]) = b_ld;
            __syncthreads();
        }
    }

    float4 bias0 = *reinterpret_cast<const float4*>(bias + n0 + tx * 4);
    float4 bias1 = *reinterpret_cast<const float4*>(bias + n0 + tx * 4 + 64);
    float bvv[8] = {bias0.x, bias0.y, bias0.z, bias0.w, bias1.x, bias1.y, bias1.z, bias1.w};

    #pragma unroll
    for (int i = 0; i < 8; i++) {
        int rloc = (i < 4) ? (ty * 4 + i) : (64 + ty * 4 + i - 4);
        size_t base = (size_t)(m0 + rloc) * N + n0;
        float4 c0, c1;
        c0.x = acc[i][0] + bvv[0]; c0.y = acc[i][1] + bvv[1];
        c0.z = acc[i][2] + bvv[2]; c0.w = acc[i][3] + bvv[3];
        c1.x = acc[i][4] + bvv[4]; c1.y = acc[i][5] + bvv[5];
        c1.z = acc[i][6] + bvv[6]; c1.w = acc[i][7] + bvv[7];
        *reinterpret_cast<float4*>(&C[base + tx * 4]) = c0;
        *reinterpret_cast<float4*>(&C[base + tx * 4 + 64]) = c1;
    }
}

// ---------------- fused LSTM step: g = Gx + h_prev @ Wh; gate nonlinearity ----
// grid 128 blocks (4 e-cols each), 128 threads.
// Each thread computes 4 dot products: b in {bl, bl+16}, gates {g2, g2+2}.
__global__ __launch_bounds__(128)
void lstm_step(const float* __restrict__ Gx,      // [B][2048] for this t (bias+x@Wx baked in)
               const float* __restrict__ HprevT,  // [E][B] or nullptr (t==0)
               const float* __restrict__ Wh,      // [E][2048]
               float* __restrict__ HoutT,         // [E][B]
               float* __restrict__ HoutRM,        // row-major h output, row = r0 + b*rstride
               float* __restrict__ Cst,           // [E][B] cell state (in/out)
               int r0, int rstride)
{
    __shared__ float sh[128 * 32];   // h chunk, transposed [k][b]   (16 KB)
    __shared__ float ws[128 * 16];   // Wh chunk [k][gate*4+el]      (8 KB)
    __shared__ float gs[512];        // assembled gates [g][el][b]   (2 KB)

    int tid = threadIdx.x;
    int e0 = blockIdx.x * 4;
    int bl = tid & 15;
    int el = (tid >> 4) & 3;
    int g2 = tid >> 6;              // 0/1
    int ga = g2, gb = g2 + 2;       // (i,f) or (j,o)

    float acc00 = 0.f, acc01 = 0.f, acc10 = 0.f, acc11 = 0.f;

    if (HprevT) {
        for (int kc = 0; kc < EE; kc += 128) {
            const float4* src = reinterpret_cast<const float4*>(HprevT + kc * 32);
            #pragma unroll
            for (int i = 0; i < 8; i++)
                reinterpret_cast<float4*>(sh)[tid + i * 128] = src[tid + i * 128];
            #pragma unroll
            for (int i = 0; i < 4; i++) {
                int idx = tid + i * 128;           // 0..511
                int g = idx & 3, kk = idx >> 2;
                float4 w = *reinterpret_cast<const float4*>(
                    Wh + (size_t)(kc + kk) * GE + g * EE + e0);
                *reinterpret_cast<float4*>(&ws[kk * 16 + g * 4]) = w;
            }
            __syncthreads();
            #pragma unroll 16
            for (int kk = 0; kk < 128; kk++) {
                float h0 = sh[kk * 32 + bl];
                float h1 = sh[kk * 32 + bl + 16];
                float wa = ws[kk * 16 + ga * 4 + el];
                float wb = ws[kk * 16 + gb * 4 + el];
                acc00 += h0 * wa; acc01 += h0 * wb;
                acc10 += h1 * wa; acc11 += h1 * wb;
            }
            __syncthreads();
        }
    }

    int eg = e0 + el;
    int b0i = bl, b1i = bl + 16;
    gs[(ga * 4 + el) * 32 + b0i] = acc00 + Gx[(size_t)b0i * GE + ga * EE + eg];
    gs[(gb * 4 + el) * 32 + b0i] = acc01 + Gx[(size_t)b0i * GE + gb * EE + eg];
    gs[(ga * 4 + el) * 32 + b1i] = acc10 + Gx[(size_t)b1i * GE + ga * EE + eg];
    gs[(gb * 4 + el) * 32 + b1i] = acc11 + Gx[(size_t)b1i * GE + gb * EE + eg];
    __syncthreads();

    int b = tid & 31;
    int el2 = tid >> 5;
    int eg2 = e0 + el2;
    float iv = gs[(0 * 4 + el2) * 32 + b];
    float jv = gs[(1 * 4 + el2) * 32 + b];
    float fv = gs[(2 * 4 + el2) * 32 + b];
    float ov = gs[(3 * 4 + el2) * 32 + b];
    float c  = Cst[eg2 * 32 + b];
    float cn = sigm(fv + 1.0f) * c + sigm(iv) * tanhf(jv);
    float hn = sigm(ov) * tanhf(cn);
    Cst[eg2 * 32 + b]   = cn;
    HoutT[eg2 * 32 + b] = hn;
    HoutRM[(size_t)(r0 + b * rstride) * EE + eg2] = hn;
}

// ---------------- softmax NLL per row (two-pass) ----------------
__global__ void softmax_nll_kernel(const float* __restrict__ logits,
                                   const int* __restrict__ labels)
{
    int row = blockIdx.x;
    const float4* lr = reinterpret_cast<const float4*>(logits + (size_t)row * VV);
    int tid = threadIdx.x;
    __shared__ float red[256];

    float m = -1e30f;
    for (int i = tid; i < VV / 4; i += 256) {
        float4 v = lr[i];
        m = fmaxf(m, fmaxf(fmaxf(v.x, v.y), fmaxf(v.z, v.w)));
    }
    red[tid] = m; __syncthreads();
    for (int s = 128; s > 0; s >>= 1) {
        if (tid < s) red[tid] = fmaxf(red[tid], red[tid + s]);
        __syncthreads();
    }
    m = red[0]; __syncthreads();

    float sum = 0.f;
    for (int i = tid; i < VV / 4; i += 256) {
        float4 v = lr[i];
        sum += expf(v.x - m) + expf(v.y - m) + expf(v.z - m) + expf(v.w - m);
    }
    red[tid] = sum; __syncthreads();
    for (int s = 128; s > 0; s >>= 1) {
        if (tid < s) red[tid] += red[tid + s];
        __syncthreads();
    }
    if (tid == 0) {
        float lv = logits[(size_t)row * VV + labels[row]];
        g_nll[row] = m + logf(red[0]) - lv;
    }
}

__global__ void perplexity_kernel(float* __restrict__ out, long long out_size) {
    __shared__ float red[256];
    int tid = threadIdx.x;
    float s = 0.f;
    for (int i = tid; i < MROWS; i += 256) s += g_nll[i];
    red[tid] = s; __syncthreads();
    for (int st = 128; st > 0; st >>= 1) {
        if (tid < st) red[tid] += red[tid + st];
        __syncthreads();
    }
    if (tid == 0 && out_size > (long long)MROWS * VV)
        out[out_size - 1] = expf(red[0] / (float)MROWS);
}

// ---------------- host launch ----------------
extern "C" void kernel_launch(void* const* d_in, const int* in_sizes, int n_in,
                              void* d_out, int out_size)
{
    const int*   inputs = (const int*)  d_in[0];
    const int*   labels = (const int*)  d_in[1];
    const float* Emat   = (const float*)d_in[2];
    const float* Wx0    = (const float*)d_in[3];
    const float* Wh0    = (const float*)d_in[4];
    const float* b0     = (const float*)d_in[5];
    const float* Wx1    = (const float*)d_in[6];
    const float* Wh1    = (const float*)d_in[7];
    const float* b1     = (const float*)d_in[8];
    const float* Wd     = (const float*)d_in[9];
    const float* bd     = (const float*)d_in[10];
    float* out = (float*)d_out;

    float *pXs, *pG, *pH0T, *pH0RM, *pH1T, *pH1RM, *pC0, *pC1;
    cudaGetSymbolAddress((void**)&pXs,   g_Xs);
    cudaGetSymbolAddress((void**)&pG,    g_G);
    cudaGetSymbolAddress((void**)&pH0T,  g_H0T);
    cudaGetSymbolAddress((void**)&pH0RM, g_H0RM);
    cudaGetSymbolAddress((void**)&pH1T,  g_H1T);
    cudaGetSymbolAddress((void**)&pH1RM, g_H1RM);
    cudaGetSymbolAddress((void**)&pC0,   g_C0);
    cudaGetSymbolAddress((void**)&pC1,   g_C1);

    // 0) zero cell states
    zero_state_kernel<<<(EE * BB + 255) / 256, 256>>>();

    // 1) embedding gather -> xs (time-major)
    embed_kernel<<<(MROWS * (EE / 4) + 255) / 256, 256>>>(inputs, Emat);

    // 2) X0 = xs @ Wx0 + b0     [8192, 2048]
    {
        dim3 grid(GE / BN, MROWS / BM);
        sgemm_bias<<<grid, 256>>>(pXs, Wx0, b0, pG, MROWS, GE, EE);
    }

    // 3) layer-0 scan
    for (int t = 0; t < TT; t++) {
        const float* hp = (t == 0) ? nullptr : (pH0T + (size_t)(t - 1) * EE * BB);
        lstm_step<<<128, 128>>>(pG + (size_t)t * BB * GE, hp, Wh0,
                                pH0T + (size_t)t * EE * BB, pH0RM, pC0,
                                /*r0=*/t * BB, /*rstride=*/1);
    }

    // 4) X1 = H0 @ Wx1 + b1     [8192, 2048]
    {
        dim3 grid(GE / BN, MROWS / BM);
        sgemm_bias<<<grid, 256>>>(pH0RM, Wx1, b1, pG, MROWS, GE, EE);
    }

    // 5) layer-1 scan (output written batch-major: row = b*T + t)
    for (int t = 0; t < TT; t++) {
        const float* hp = (t == 0) ? nullptr : (pH1T + (size_t)(t - 1) * EE * BB);
        lstm_step<<<128, 128>>>(pG + (size_t)t * BB * GE, hp, Wh1,
                                pH1T + (size_t)t * EE * BB, pH1RM, pC1,
                                /*r0=*/t, /*rstride=*/TT);
    }

    // 6) logits = H1RM @ Wd + bd   [8192, 16000]  -> directly into d_out
    {
        dim3 grid(VV / BN, MROWS / BM);
        sgemm_bias<<<grid, 256>>>(pH1RM, Wd, bd, out, MROWS, VV, EE);
    }

    // 7) per-row NLL
    softmax_nll_kernel<<<MROWS, 256>>>(out, labels);

    // 8) perplexity scalar
    perplexity_kernel<<<1, 256>>>(out, (long long)out_size);
}

// round 3
// speedup vs baseline: 1.2558x; 1.2558x over previous
#include <cuda_runtime.h>
#include <cuda_bf16.h>
#include <cstdint>
#include <math.h>

// Problem dims
#define VV 16000
#define BB 32
#define TT 256
#define EE 512
#define GE 2048          // 4*E
#define MROWS 8192       // B*T

#define NBLK 128
#define NTHR 256

// ---------------- scratch (device globals; no allocation allowed) -------------
__device__ __align__(16) float g_Xs  [(size_t)MROWS * EE];     // xs time-major [t*B+b][E]
__device__ __align__(16) float g_G   [(size_t)MROWS * GE];     // x@Wx+b (reused per layer)
__device__ __align__(16) float g_H0RM[(size_t)MROWS * EE];     // layer0 h, time-major rows
__device__ __align__(16) float g_H1RM[(size_t)MROWS * EE];     // layer1 h, batch-major rows
__device__ __align__(16) float g_Hping[2 * BB * EE];           // h ping-pong [B][E]
__device__ float g_nll [MROWS];
__device__ unsigned g_bar_cnt;
__device__ unsigned g_bar_gen;

// ---------------- helpers ----------------
__device__ __forceinline__ float sigm(float x) { return 1.0f / (1.0f + expf(-x)); }

__device__ __forceinline__ unsigned ld_acq(const unsigned* p) {
    unsigned v;
    asm volatile("ld.acquire.gpu.u32 %0, [%1];" : "=r"(v) : "l"(p) : "memory");
    return v;
}

__device__ __forceinline__ void cp_async16(unsigned int dst, const void* src) {
    asm volatile("cp.async.cg.shared.global [%0], [%1], 16;" :: "r"(dst), "l"(src));
}
__device__ __forceinline__ void cp_commit() { asm volatile("cp.async.commit_group;"); }
template<int N> __device__ __forceinline__ void cp_wait() {
    asm volatile("cp.async.wait_group %0;" :: "n"(N));
}

__device__ __forceinline__ void grid_barrier(unsigned& mygen) {
    __syncthreads();
    if (threadIdx.x == 0) {
        unsigned a = atomicAdd(&g_bar_cnt, 1u);
        if (a == NBLK - 1) {
            g_bar_cnt = 0u;
            __threadfence();
            atomicAdd(&g_bar_gen, 1u);
        } else {
            while (ld_acq(&g_bar_gen) == mygen) { }
        }
        mygen++;
    }
    __syncthreads();
}

// ---------------- init: reset barrier state ----------------
__global__ void init_kernel() {
    if (threadIdx.x == 0) { g_bar_cnt = 0u; g_bar_gen = 0u; }
}

// ---------------- embedding gather ----------------
__global__ void embed_kernel(const int* __restrict__ inputs, const float* __restrict__ Emat) {
    int idx = blockIdx.x * blockDim.x + threadIdx.x;
    if (idx >= MROWS * (EE / 4)) return;
    int r  = idx >> 7;
    int e4 = idx & 127;
    int t = r >> 5;
    int b = r & 31;
    int tok = inputs[b * TT + t];
    reinterpret_cast<float4*>(g_Xs)[(size_t)r * 128 + e4] =
        reinterpret_cast<const float4*>(Emat)[(size_t)tok * 128 + e4];
}

// ---------------- SGEMM: C[M,N] = A[M,K]*B[K,N] + bias[N] ----------------
#define BM 128
#define BN 128
#define BK 8

__global__ __launch_bounds__(256, 2)
void sgemm_bias(const float* __restrict__ A, const float* __restrict__ Bm,
                const float* __restrict__ bias, float* __restrict__ C,
                int M, int N, int K)
{
    __shared__ __align__(16) float As[2][BK][BM];
    __shared__ __align__(16) float Bs[2][BK][BN];

    int tid = threadIdx.x;
    int n0 = blockIdx.x * BN;
    int m0 = blockIdx.y * BM;

    int aRow = tid >> 1;
    int aK   = (tid & 1) * 4;
    int bK   = tid >> 5;
    int bN   = (tid & 31) * 4;

    int tx = tid & 15;
    int ty = tid >> 4;

    const float* Aptr = A + (size_t)(m0 + aRow) * K + aK;
    const float* Bptr = Bm + (size_t)bK * N + n0 + bN;

    float4 a_ld = *reinterpret_cast<const float4*>(Aptr);
    float4 b_ld = *reinterpret_cast<const float4*>(Bptr);

    As[0][aK + 0][aRow] = a_ld.x;
    As[0][aK + 1][aRow] = a_ld.y;
    As[0][aK + 2][aRow] = a_ld.z;
    As[0][aK + 3][aRow] = a_ld.w;
    *reinterpret_cast<float4*>(&Bs[0][bK][bN]) = b_ld;
    __syncthreads();

    float acc[8][8];
    #pragma unroll
    for (int i = 0; i < 8; i++)
        #pragma unroll
        for (int j = 0; j < 8; j++) acc[i][j] = 0.0f;

    int NT = K / BK;
    int buf = 0;
    for (int kt = 0; kt < NT; kt++) {
        if (kt + 1 < NT) {
            a_ld = *reinterpret_cast<const float4*>(Aptr + (kt + 1) * BK);
            b_ld = *reinterpret_cast<const float4*>(Bptr + (size_t)(kt + 1) * BK * N);
        }
        #pragma unroll
        for (int k = 0; k < BK; k++) {
            float4 a0 = *reinterpret_cast<float4*>(&As[buf][k][ty * 4]);
            float4 a1 = *reinterpret_cast<float4*>(&As[buf][k][ty * 4 + 64]);
            float4 b0 = *reinterpret_cast<float4*>(&Bs[buf][k][tx * 4]);
            float4 b1 = *reinterpret_cast<float4*>(&Bs[buf][k][tx * 4 + 64]);
            float av[8] = {a0.x, a0.y, a0.z, a0.w, a1.x, a1.y, a1.z, a1.w};
            float bv[8] = {b0.x, b0.y, b0.z, b0.w, b1.x, b1.y, b1.z, b1.w};
            #pragma unroll
            for (int i = 0; i < 8; i++)
                #pragma unroll
                for (int j = 0; j < 8; j++)
                    acc[i][j] += av[i] * bv[j];
        }
        if (kt + 1 < NT) {
            buf ^= 1;
            As[buf][aK + 0][aRow] = a_ld.x;
            As[buf][aK + 1][aRow] = a_ld.y;
            As[buf][aK + 2][aRow] = a_ld.z;
            As[buf][aK + 3][aRow] = a_ld.w;
            *reinterpret_cast<float4*>(&Bs[buf][bK][bN]) = b_ld;
            __syncthreads();
        }
    }

    float4 bias0 = *reinterpret_cast<const float4*>(bias + n0 + tx * 4);
    float4 bias1 = *reinterpret_cast<const float4*>(bias + n0 + tx * 4 + 64);
    float bvv[8] = {bias0.x, bias0.y, bias0.z, bias0.w, bias1.x, bias1.y, bias1.z, bias1.w};

    #pragma unroll
    for (int i = 0; i < 8; i++) {
        int rloc = (i < 4) ? (ty * 4 + i) : (64 + ty * 4 + i - 4);
        size_t base = (size_t)(m0 + rloc) * N + n0;
        float4 c0, c1;
        c0.x = acc[i][0] + bvv[0]; c0.y = acc[i][1] + bvv[1];
        c0.z = acc[i][2] + bvv[2]; c0.w = acc[i][3] + bvv[3];
        c1.x = acc[i][4] + bvv[4]; c1.y = acc[i][5] + bvv[5];
        c1.z = acc[i][6] + bvv[6]; c1.w = acc[i][7] + bvv[7];
        *reinterpret_cast<float4*>(&C[base + tx * 4]) = c0;
        *reinterpret_cast<float4*>(&C[base + tx * 4 + 64]) = c1;
    }
}

// ---------------- persistent LSTM layer ----------------
// 128 blocks x 256 threads, all co-resident. Block owns 16 gate-cols
// (4 e-values x 4 gates), Wh slice cached in smem for all 256 steps.
// h ping-pongs through g_Hping with one software grid barrier per step.

#define SM_WS 0
#define SM_SH (16 * 512)                 // 8192 floats
#define SM_GS (SM_SH + 32 * 512)         // 24576
#define SM_CS (SM_GS + 512)              // 25088
#define SM_FLOATS (SM_CS + 128)          // 25216 -> 100864 bytes

__global__ __launch_bounds__(NTHR, 1)
void lstm_layer_persistent(const float* __restrict__ Gx,   // [T*B][2048], rows t*32+b
                           const float* __restrict__ Wh,   // [512][2048]
                           float* __restrict__ HoutRM,     // row = t*rA + b*rB
                           int rA, int rB, unsigned gen_base)
{
    extern __shared__ float smem[];
    float* ws = smem + SM_WS;
    float* sh = smem + SM_SH;
    float* gs = smem + SM_GS;
    float* cs = smem + SM_CS;

    int tid = threadIdx.x;
    int e0 = blockIdx.x * 4;
    int b  = tid & 31;
    int cg = tid >> 5;                 // 0..7
    int c0 = cg * 2, c1 = c0 + 1;
    int col0 = ((c0 >> 2) << 9) + e0 + (c0 & 3);
    int col1 = ((c1 >> 2) << 9) + e0 + (c1 & 3);
    int bx7 = b & 7;

    // one-time: load Wh slice into smem ws[c][k]
    for (int i = tid; i < 16 * 512; i += NTHR) {
        int c = i & 15, k = i >> 4;
        ws[c * 512 + k] = Wh[(size_t)k * 2048 + ((c >> 2) << 9) + e0 + (c & 3)];
    }
    if (tid < 128) cs[tid] = 0.0f;

    unsigned mygen = gen_base;
    unsigned int sh_u32 = (unsigned int)__cvta_generic_to_shared(sh);
    const float4* ws4 = (const float4*)ws;
    const float4* hp  = (const float4*)sh + b * 128;
    const float4* wp0 = ws4 + c0 * 128;
    const float4* wp1 = ws4 + c1 * 128;
    __syncthreads();

    #pragma unroll 1
    for (int t = 0; t < TT; t++) {
        const float* hg_r = g_Hping + ((t & 1) ? (BB * EE) : 0);
        float*       hg_w = g_Hping + ((t & 1) ? 0 : (BB * EE));

        float gx0 = Gx[(size_t)(t * 32 + b) * 2048 + col0];
        float gx1 = Gx[(size_t)(t * 32 + b) * 2048 + col1];

        float acc0 = 0.0f, acc1 = 0.0f;

        if (t > 0) {
            // issue all 4 h chunks (cp.async, swizzled dst)
            #pragma unroll
            for (int ch = 0; ch < 4; ch++) {
                #pragma unroll
                for (int q = 0; q < 4; q++) {
                    int m  = tid + q * 256;            // 0..1023
                    int bb = m >> 5, kk = m & 31;
                    int src4 = bb * 128 + ch * 32 + kk;
                    int dst4 = bb * 128 + (((ch * 32 + kk)) ^ (bb & 7));
                    cp_async16(sh_u32 + (unsigned int)dst4 * 16u,
                               (const float4*)hg_r + src4);
                }
                cp_commit();
            }

            #define LSTM_CHUNK(CH)                                            \
            {                                                                  \
                _Pragma("unroll")                                              \
                for (int kk = 0; kk < 32; kk++) {                              \
                    float4 hv = hp[((CH) * 32 + kk) ^ bx7];                    \
                    float4 w0 = wp0[(CH) * 32 + kk];                           \
                    float4 w1 = wp1[(CH) * 32 + kk];                           \
                    acc0 += hv.x * w0.x + hv.y * w0.y + hv.z * w0.z + hv.w * w0.w; \
                    acc1 += hv.x * w1.x + hv.y * w1.y + hv.z * w1.z + hv.w * w1.w; \
                }                                                              \
            }

            cp_wait<3>(); __syncthreads(); LSTM_CHUNK(0)
            cp_wait<2>(); __syncthreads(); LSTM_CHUNK(1)
            cp_wait<1>(); __syncthreads(); LSTM_CHUNK(2)
            cp_wait<0>(); __syncthreads(); LSTM_CHUNK(3)
            #undef LSTM_CHUNK
        }

        // assemble gates
        gs[c0 * 32 + b] = acc0 + gx0;
        gs[c1 * 32 + b] = acc1 + gx1;
        __syncthreads();

        if (tid < 128) {
            int b2 = tid & 31, e2 = tid >> 5;
            float iv = gs[(0  + e2) * 32 + b2];
            float jv = gs[(4  + e2) * 32 + b2];
            float fv = gs[(8  + e2) * 32 + b2];
            float ov = gs[(12 + e2) * 32 + b2];
            float cold = cs[tid];
            float cn = sigm(fv + 1.0f) * cold + sigm(iv) * tanhf(jv);
            float hn = sigm(ov) * tanhf(cn);
            cs[tid] = cn;
            hg_w[b2 * 512 + e0 + e2] = hn;
            HoutRM[(size_t)(t * rA + b2 * rB) * 512 + e0 + e2] = hn;
            __threadfence();
        }
        grid_barrier(mygen);
    }
}

// ---------------- softmax NLL per row (two-pass) ----------------
__global__ void softmax_nll_kernel(const float* __restrict__ logits,
                                   const int* __restrict__ labels)
{
    int row = blockIdx.x;
    const float4* lr = reinterpret_cast<const float4*>(logits + (size_t)row * VV);
    int tid = threadIdx.x;
    __shared__ float red[256];

    float m = -1e30f;
    for (int i = tid; i < VV / 4; i += 256) {
        float4 v = lr[i];
        m = fmaxf(m, fmaxf(fmaxf(v.x, v.y), fmaxf(v.z, v.w)));
    }
    red[tid] = m; __syncthreads();
    for (int s = 128; s > 0; s >>= 1) {
        if (tid < s) red[tid] = fmaxf(red[tid], red[tid + s]);
        __syncthreads();
    }
    m = red[0]; __syncthreads();

    float sum = 0.f;
    for (int i = tid; i < VV / 4; i += 256) {
        float4 v = lr[i];
        sum += expf(v.x - m) + expf(v.y - m) + expf(v.z - m) + expf(v.w - m);
    }
    red[tid] = sum; __syncthreads();
    for (int s = 128; s > 0; s >>= 1) {
        if (tid < s) red[tid] += red[tid + s];
        __syncthreads();
    }
    if (tid == 0) {
        float lv = logits[(size_t)row * VV + labels[row]];
        g_nll[row] = m + logf(red[0]) - lv;
    }
}

__global__ void perplexity_kernel(float* __restrict__ out, long long out_size) {
    __shared__ float red[256];
    int tid = threadIdx.x;
    float s = 0.f;
    for (int i = tid; i < MROWS; i += 256) s += g_nll[i];
    red[tid] = s; __syncthreads();
    for (int st = 128; st > 0; st >>= 1) {
        if (tid < st) red[tid] += red[tid + st];
        __syncthreads();
    }
    if (tid == 0 && out_size > (long long)MROWS * VV)
        out[out_size - 1] = expf(red[0] / (float)MROWS);
}

// ---------------- host launch ----------------
extern "C" void kernel_launch(void* const* d_in, const int* in_sizes, int n_in,
                              void* d_out, int out_size)
{
    const int*   inputs = (const int*)  d_in[0];
    const int*   labels = (const int*)  d_in[1];
    const float* Emat   = (const float*)d_in[2];
    const float* Wx0    = (const float*)d_in[3];
    const float* Wh0    = (const float*)d_in[4];
    const float* b0     = (const float*)d_in[5];
    const float* Wx1    = (const float*)d_in[6];
    const float* Wh1    = (const float*)d_in[7];
    const float* b1     = (const float*)d_in[8];
    const float* Wd     = (const float*)d_in[9];
    const float* bd     = (const float*)d_in[10];
    float* out = (float*)d_out;

    float *pXs, *pG, *pH0RM, *pH1RM;
    cudaGetSymbolAddress((void**)&pXs,   g_Xs);
    cudaGetSymbolAddress((void**)&pG,    g_G);
    cudaGetSymbolAddress((void**)&pH0RM, g_H0RM);
    cudaGetSymbolAddress((void**)&pH1RM, g_H1RM);

    const int lstm_smem = SM_FLOATS * 4;
    cudaFuncSetAttribute(lstm_layer_persistent,
                         cudaFuncAttributeMaxDynamicSharedMemorySize, lstm_smem);

    // 0) reset barrier state
    init_kernel<<<1, 32>>>();

    // 1) embedding gather -> xs (time-major)
    embed_kernel<<<(MROWS * (EE / 4) + 255) / 256, 256>>>(inputs, Emat);

    // 2) X0 = xs @ Wx0 + b0     [8192, 2048]
    {
        dim3 grid(GE / BN, MROWS / BM);
        sgemm_bias<<<grid, 256>>>(pXs, Wx0, b0, pG, MROWS, GE, EE);
    }

    // 3) layer-0 persistent scan (time-major output rows r = t*32 + b)
    lstm_layer_persistent<<<NBLK, NTHR, lstm_smem>>>(pG, Wh0, pH0RM,
                                                     /*rA=*/32, /*rB=*/1,
                                                     /*gen_base=*/0u);

    // 4) X1 = H0 @ Wx1 + b1     [8192, 2048]
    {
        dim3 grid(GE / BN, MROWS / BM);
        sgemm_bias<<<grid, 256>>>(pH0RM, Wx1, b1, pG, MROWS, GE, EE);
    }

    // 5) layer-1 persistent scan (batch-major output rows r = b*256 + t)
    lstm_layer_persistent<<<NBLK, NTHR, lstm_smem>>>(pG, Wh1, pH1RM,
                                                     /*rA=*/1, /*rB=*/TT,
                                                     /*gen_base=*/(unsigned)TT);

    // 6) logits = H1 @ Wd + bd   [8192, 16000] -> d_out
    {
        dim3 grid(VV / BN, MROWS / BM);
        sgemm_bias<<<grid, 256>>>(pH1RM, Wd, bd, out, MROWS, VV, EE);
    }

    // 7) per-row NLL
    softmax_nll_kernel<<<MROWS, 256>>>(out, labels);

    // 8) perplexity scalar
    perplexity_kernel<<<1, 256>>>(out, (long long)out_size);
}